// round 3
// baseline (speedup 1.0000x reference)
#include <cuda_runtime.h>

#define Hdim 1024
#define H2   512
#define Bb   4
#define Ss   2048
#define Kk   4
#define NBLK 96
#define RPB  16      // weight rows per block (96*16 = 1536 = 1024 rec + 512 tau)
#define NT   128     // threads per block (4 warps, 4 rows each)
#define DTc  0.1f
#define SCALEc 0.01f

// ---------------- device scratch (static, no allocation) ----------------
__device__ float    g_h[Bb * Hdim];          // recurrent state
__device__ float    g_acc[Ss * 32];          // per-step scalars [t][b*8 + {Ztau,Sf,Sff,Shf}]
__device__ float    g_pretau[(size_t)Bb * Ss * H2]; // x-part of tau MLP (16MB)
__device__ unsigned g_barA, g_barB;          // monotonic grid barriers

// ---------------- reset (runs every launch; graph-replay safe) ----------
__global__ void reset_kernel() {
    int i = blockIdx.x * blockDim.x + threadIdx.x;
    if (i < Ss * 32)  g_acc[i] = 0.f;
    if (i < Bb * Hdim) g_h[i] = 0.f;
    if (i == 0) { g_barA = 0u; g_barB = 0u; }
}

// ---------------- pre-tau GEMM: C[p][m] = b1[m] + sum_i X[p][i]*tw1[i][m] ---
// X: [8192,1024], tw1 top half: [1024,512] row-major. BM=128 BN=64 BK=16.
__global__ void pretau_gemm(const float* __restrict__ X,
                            const float* __restrict__ tw1,
                            const float* __restrict__ b1) {
    __shared__ float As[16][128];
    __shared__ float Bs[16][64];
    const int tx = threadIdx.x;                  // 256 threads
    const int row0 = blockIdx.y * 128;
    const int col0 = blockIdx.x * 64;
    const int tr = tx >> 4, tc = tx & 15;        // 16x16 thread grid, 8x4 micro-tile
    float acc[8][4];
#pragma unroll
    for (int i = 0; i < 8; i++)
#pragma unroll
        for (int j = 0; j < 4; j++) acc[i][j] = 0.f;

    for (int k0 = 0; k0 < Hdim; k0 += 16) {
#pragma unroll
        for (int l = 0; l < 2; l++) {
            int f = tx + l * 256;                // 512 float4 loads for 128x16
            int r = f >> 2, c4 = (f & 3) << 2;
            float4 v = *reinterpret_cast<const float4*>(X + (size_t)(row0 + r) * Hdim + k0 + c4);
            As[c4 + 0][r] = v.x; As[c4 + 1][r] = v.y; As[c4 + 2][r] = v.z; As[c4 + 3][r] = v.w;
        }
        {
            int r = tx >> 4, c4 = (tx & 15) << 2;
            *reinterpret_cast<float4*>(&Bs[r][c4]) =
                *reinterpret_cast<const float4*>(tw1 + (size_t)(k0 + r) * H2 + col0 + c4);
        }
        __syncthreads();
#pragma unroll
        for (int k = 0; k < 16; k++) {
            float a[8], bb[4];
#pragma unroll
            for (int i = 0; i < 8; i++) a[i] = As[k][tr * 8 + i];
#pragma unroll
            for (int j = 0; j < 4; j++) bb[j] = Bs[k][tc * 4 + j];
#pragma unroll
            for (int i = 0; i < 8; i++)
#pragma unroll
                for (int j = 0; j < 4; j++) acc[i][j] += a[i] * bb[j];
        }
        __syncthreads();
    }
    float4 bv = *reinterpret_cast<const float4*>(b1 + col0 + tc * 4);
#pragma unroll
    for (int i = 0; i < 8; i++) {
        float4 o = make_float4(acc[i][0] + bv.x, acc[i][1] + bv.y,
                               acc[i][2] + bv.z, acc[i][3] + bv.w);
        *reinterpret_cast<float4*>(&g_pretau[(size_t)(row0 + tr * 8 + i) * H2 + col0 + tc * 4]) = o;
    }
}

// ---------------- conv pass: out = 0.99 * shortconv(x) -------------------
__global__ void conv_kernel(const float* __restrict__ X,
                            const float* __restrict__ cw,
                            float* __restrict__ out) {
    int idx = blockIdx.x * blockDim.x + threadIdx.x;        // one float4 of H per thread
    if (idx >= Bb * Ss * (Hdim / 4)) return;
    int t = (idx >> 8) & (Ss - 1);
    int b = idx >> 19;                                      // 256*2048 = 2^19
    int j = (idx & 255) << 2;
    float w[4][4];
#pragma unroll
    for (int r = 0; r < 4; r++) {
        float4 wr = *reinterpret_cast<const float4*>(cw + (j + r) * 4);
        w[r][0] = wr.x; w[r][1] = wr.y; w[r][2] = wr.z; w[r][3] = wr.w;
    }
    const float* xb = X + (size_t)b * Ss * Hdim;
    float4 acc = make_float4(0.f, 0.f, 0.f, 0.f);
#pragma unroll
    for (int k = 0; k < 4; k++) {
        int tt = t - 3 + k;
        if (tt >= 0) {
            float4 xv = *reinterpret_cast<const float4*>(xb + (size_t)tt * Hdim + j);
            acc.x += w[0][k] * xv.x; acc.y += w[1][k] * xv.y;
            acc.z += w[2][k] * xv.z; acc.w += w[3][k] * xv.w;
        }
    }
    acc.x *= (1.f - SCALEc); acc.y *= (1.f - SCALEc);
    acc.z *= (1.f - SCALEc); acc.w *= (1.f - SCALEc);
    *reinterpret_cast<float4*>(out + (size_t)idx * 4) = acc;
}

// ---------------- persistent liquid recurrence ---------------------------
// 96 blocks, all co-resident. Blocks 0..63 own rec rows (f path + LN),
// blocks 64..95 own tau-hidden rows (z path). Weights SMEM-resident.
__global__ void __launch_bounds__(NT, 1)
liquid_kernel(const float* __restrict__ X,
              const float* __restrict__ Wrec,
              const float* __restrict__ tw1,
              const float* __restrict__ tw2,
              const float* __restrict__ tb2p,
              const float* __restrict__ lngp,
              const float* __restrict__ lnbp,
              float* __restrict__ out) {
    extern __shared__ float sm[];
    float* w_s  = sm;                       // RPB*Hdim = 16384
    float* h_s  = w_s + RPB * Hdim;         // 4*1024  = 4096
    float* dots = h_s + Bb * Hdim;          // 64
    float* fz_s = dots + 64;                // 64
    float* lng  = fz_s + 64;                // 16
    float* lnb  = lng + 16;                 // 16
    float* w2s  = lnb + 16;                 // 16
    float* xpre = w2s + 16;                 // 64
    float* shs  = xpre + 64;                // 4
    float* shhs = shs + 4;                  // 4
    float* scal = shhs + 4;                 // 16 : a[4] oma[4] mu[4] rstd[4]
    float* red  = scal + 16;                // 64

    const int tid  = threadIdx.x;
    const int warp = tid >> 5, lane = tid & 31;
    const int r0   = blockIdx.x * RPB;
    const bool isrec = (r0 < Hdim);
    const float tb2 = *tb2p;
    const unsigned NBu = gridDim.x;

    // ---- load this block's 16 weight rows into SMEM (once) ----
    if (isrec) {
        for (int idx = tid; idx < RPB * (Hdim / 4); idx += NT) {
            int rl = idx >> 8; int i4 = (idx & 255) << 2;
            *reinterpret_cast<float4*>(&w_s[rl * Hdim + i4]) =
                *reinterpret_cast<const float4*>(Wrec + (size_t)(r0 + rl) * Hdim + i4);
        }
        if (tid < RPB) { lng[tid] = lngp[r0 + tid]; lnb[tid] = lnbp[r0 + tid]; }
    } else {
        int m0 = r0 - Hdim;
        for (int idx = tid; idx < RPB * Hdim; idx += NT) {
            int rl = idx & (RPB - 1); int i = idx >> 4;   // gather transpose of tau_w1 bottom half
            w_s[rl * Hdim + i] = tw1[(size_t)(Hdim + i) * H2 + m0 + rl];
        }
        if (tid < RPB) w2s[tid] = tw2[r0 - Hdim + tid];
    }
    __syncthreads();

    for (int t = 0; t < Ss; t++) {
        // ---- Phase A1: load h (L1-bypassing), local Sh/Shh partials ----
        float psh[4], pshh[4];
#pragma unroll
        for (int b = 0; b < 4; b++) { psh[b] = 0.f; pshh[b] = 0.f; }
#pragma unroll
        for (int b = 0; b < 4; b++) {
#pragma unroll
            for (int l = 0; l < 2; l++) {
                int i4 = (tid + l * NT) << 2;
                float4 v = __ldcg(reinterpret_cast<const float4*>(&g_h[b * Hdim + i4]));
                *reinterpret_cast<float4*>(&h_s[b * Hdim + i4]) = v;
                psh[b]  += v.x + v.y + v.z + v.w;
                pshh[b] += v.x * v.x + v.y * v.y + v.z * v.z + v.w * v.w;
            }
        }
        if (tid < 64) {            // prefetch x_t / pre_tau for this block's rows
            int b = tid >> 4, rl = tid & 15;
            if (isrec) xpre[tid] = X[(size_t)(b * Ss + t) * Hdim + r0 + rl];
            else       xpre[tid] = g_pretau[(size_t)(b * Ss + t) * H2 + (r0 - Hdim) + rl];
        }
        if (isrec) {
#pragma unroll
            for (int b = 0; b < 4; b++) {
                float v1 = psh[b], v2 = pshh[b];
#pragma unroll
                for (int off = 16; off > 0; off >>= 1) {
                    v1 += __shfl_down_sync(0xffffffffu, v1, off);
                    v2 += __shfl_down_sync(0xffffffffu, v2, off);
                }
                if (lane == 0) { red[warp * 8 + b] = v1; red[warp * 8 + 4 + b] = v2; }
            }
        }
        __syncthreads();
        if (isrec && tid < 8) {
            float s = 0.f;
#pragma unroll
            for (int w = 0; w < 4; w++) s += red[w * 8 + tid];
            if (tid < 4) shs[tid] = s; else shhs[tid - 4] = s;
        }

        // ---- Phase A2: dots — warp owns 4 rows, all 4 batches ----
        const int rbase = warp * 4;
        float av[4][4];
#pragma unroll
        for (int r = 0; r < 4; r++)
#pragma unroll
            for (int b = 0; b < 4; b++) av[r][b] = 0.f;
#pragma unroll
        for (int c = 0; c < 8; c++) {
            int base = c * 128 + lane * 4;
            float4 w0 = *reinterpret_cast<const float4*>(&w_s[(rbase + 0) * Hdim + base]);
            float4 w1 = *reinterpret_cast<const float4*>(&w_s[(rbase + 1) * Hdim + base]);
            float4 w2 = *reinterpret_cast<const float4*>(&w_s[(rbase + 2) * Hdim + base]);
            float4 w3 = *reinterpret_cast<const float4*>(&w_s[(rbase + 3) * Hdim + base]);
#pragma unroll
            for (int b = 0; b < 4; b++) {
                float4 hv = *reinterpret_cast<const float4*>(&h_s[b * Hdim + base]);
                av[0][b] += w0.x * hv.x + w0.y * hv.y + w0.z * hv.z + w0.w * hv.w;
                av[1][b] += w1.x * hv.x + w1.y * hv.y + w1.z * hv.z + w1.w * hv.w;
                av[2][b] += w2.x * hv.x + w2.y * hv.y + w2.z * hv.z + w2.w * hv.w;
                av[3][b] += w3.x * hv.x + w3.y * hv.y + w3.z * hv.z + w3.w * hv.w;
            }
        }
#pragma unroll
        for (int r = 0; r < 4; r++)
#pragma unroll
            for (int b = 0; b < 4; b++) {
                float v = av[r][b];
#pragma unroll
                for (int off = 16; off > 0; off >>= 1) v += __shfl_down_sync(0xffffffffu, v, off);
                if (lane == 0) dots[(rbase + r) * 4 + b] = v;
            }
        __syncthreads();

        // ---- Phase A3: f/z + scalar partial atomics ----
        if (tid < 64) {
            int b = tid >> 4, rl = tid & 15;
            float d = dots[rl * 4 + b];
            float* accp = &g_acc[t * 32 + b * 8];
            if (isrec) {
                float f = tanhf(xpre[tid] + d);
                fz_s[tid] = f;
                float hv = h_s[b * Hdim + r0 + rl];
                float pf = f, pff = f * f, phf = hv * f;
#pragma unroll
                for (int off = 8; off > 0; off >>= 1) {
                    pf  += __shfl_down_sync(0xffffffffu, pf,  off, 16);
                    pff += __shfl_down_sync(0xffffffffu, pff, off, 16);
                    phf += __shfl_down_sync(0xffffffffu, phf, off, 16);
                }
                if (rl == 0) {
                    atomicAdd(accp + 1, pf);
                    atomicAdd(accp + 2, pff);
                    atomicAdd(accp + 3, phf);
                }
            } else {
                float z = tanhf(xpre[tid] + d);
                float pz = z * w2s[rl];
#pragma unroll
                for (int off = 8; off > 0; off >>= 1)
                    pz += __shfl_down_sync(0xffffffffu, pz, off, 16);
                if (rl == 0) atomicAdd(accp + 0, pz);
            }
        }
        __threadfence();
        __syncthreads();
        // ---- grid barrier A ----
        if (tid == 0) {
            atomicAdd(&g_barA, 1u);
            unsigned target = (unsigned)(t + 1) * NBu, v;
            do { asm volatile("ld.acquire.gpu.u32 %0, [%1];" : "=r"(v) : "l"(&g_barA) : "memory"); }
            while (v < target);
        }
        __syncthreads();

        // ---- Phase B: tau + analytic LN + write h/out (rec blocks) ----
        if (isrec && tid < 4) {
            const float* accp = &g_acc[t * 32 + tid * 8];
            float Zt  = __ldcg(accp + 0);
            float Sf  = __ldcg(accp + 1);
            float Sff = __ldcg(accp + 2);
            float Shf = __ldcg(accp + 3);
            float sig = 1.f / (1.f + expf(-(Zt + tb2)));
            float tau = 1.f + 4.f * sig;
            float a = DTc / tau, oma = 1.f - a;
            float mu  = (oma * shs[tid] + a * Sf) * (1.f / (float)Hdim);
            float sy2 = oma * oma * shhs[tid] + 2.f * a * oma * Shf + a * a * Sff;
            float var = sy2 * (1.f / (float)Hdim) - mu * mu;
            scal[tid] = a; scal[4 + tid] = oma; scal[8 + tid] = mu;
            scal[12 + tid] = rsqrtf(var + 1e-5f);
        }
        __syncthreads();
        if (isrec && tid < 64) {
            int b = tid >> 4, rl = tid & 15;
            int j = r0 + rl;
            float y  = scal[4 + b] * h_s[b * Hdim + j] + scal[b] * fz_s[tid];
            float hn = (y - scal[8 + b]) * scal[12 + b] * lng[rl] + lnb[rl];
            g_h[b * Hdim + j] = hn;
            size_t o = (size_t)(b * Ss + t) * Hdim + j;
            out[o] = out[o] + SCALEc * hn;        // out pre-filled with 0.99*sc
        }
        __threadfence();
        __syncthreads();
        // ---- grid barrier B ----
        if (tid == 0) {
            atomicAdd(&g_barB, 1u);
            unsigned target = (unsigned)(t + 1) * NBu, v;
            do { asm volatile("ld.acquire.gpu.u32 %0, [%1];" : "=r"(v) : "l"(&g_barB) : "memory"); }
            while (v < target);
        }
        __syncthreads();
    }
}

// ---------------- launch --------------------------------------------------
extern "C" void kernel_launch(void* const* d_in, const int* in_sizes, int n_in,
                              void* d_out, int out_size) {
    const float* X   = (const float*)d_in[0];
    const float* cw  = (const float*)d_in[1];
    const float* Wr  = (const float*)d_in[2];
    const float* tw1 = (const float*)d_in[3];
    const float* tb1 = (const float*)d_in[4];
    const float* tw2 = (const float*)d_in[5];
    const float* tb2 = (const float*)d_in[6];
    const float* lg  = (const float*)d_in[7];
    const float* lb  = (const float*)d_in[8];
    float* out = (float*)d_out;

    const int smem_bytes = (RPB * Hdim + Bb * Hdim + 64 + 64 + 16 + 16 + 16 + 64 + 4 + 4 + 16 + 64) * 4;
    cudaFuncSetAttribute(liquid_kernel, cudaFuncAttributeMaxDynamicSharedMemorySize, smem_bytes);

    reset_kernel<<<256, 256>>>();

    dim3 ggrid(H2 / 64, (Bb * Ss) / 128);
    pretau_gemm<<<ggrid, 256>>>(X, tw1, tb1);

    conv_kernel<<<(Bb * Ss * (Hdim / 4)) / 256, 256>>>(X, cw, out);

    liquid_kernel<<<NBLK, NT, smem_bytes>>>(X, Wr, tw1, tw2, tb2, lg, lb, out);
}

// round 5
// speedup vs baseline: 1.2995x; 1.2995x over previous
#include <cuda_runtime.h>

#define Hdim 1024
#define H2   512
#define Bb   4
#define Ss   2048
#define NBLK 96
#define RPB  16      // weight rows per block (96*16 = 1536 = 1024 rec + 512 tau)
#define NT   256     // 8 warps
#define DTc  0.1f
#define SCALEc 0.01f

// ---------------- device scratch (static, no allocation) ----------------
__device__ float    g_fz[2 * Bb * Hdim];     // double-buffered f vector (rec rows)
__device__ float    g_acc[Ss * 32];          // per-step scalars [t][b*8 + {Ztau,Sf,Sff,Shf}]
__device__ float    g_pretau[(size_t)Bb * Ss * H2]; // x-part of tau MLP (16MB)
__device__ unsigned g_bar;                   // monotonic grid barrier

// ---------------- reset (runs every launch; graph-replay safe) ----------
__global__ void reset_kernel() {
    int i = blockIdx.x * blockDim.x + threadIdx.x;
    if (i < Ss * 32) g_acc[i] = 0.f;
    if (i == 0) g_bar = 0u;
}

// ---------------- pre-tau GEMM: C[p][m] = b1[m] + sum_i X[p][i]*tw1[i][m] ---
__global__ void pretau_gemm(const float* __restrict__ X,
                            const float* __restrict__ tw1,
                            const float* __restrict__ b1) {
    __shared__ float As[16][128];
    __shared__ float Bs[16][64];
    const int tx = threadIdx.x;                  // 256 threads
    const int row0 = blockIdx.y * 128;
    const int col0 = blockIdx.x * 64;
    const int tr = tx >> 4, tc = tx & 15;        // 16x16 thread grid, 8x4 micro-tile
    float acc[8][4];
#pragma unroll
    for (int i = 0; i < 8; i++)
#pragma unroll
        for (int j = 0; j < 4; j++) acc[i][j] = 0.f;

    for (int k0 = 0; k0 < Hdim; k0 += 16) {
#pragma unroll
        for (int l = 0; l < 2; l++) {
            int f = tx + l * 256;
            int r = f >> 2, c4 = (f & 3) << 2;
            float4 v = *reinterpret_cast<const float4*>(X + (size_t)(row0 + r) * Hdim + k0 + c4);
            As[c4 + 0][r] = v.x; As[c4 + 1][r] = v.y; As[c4 + 2][r] = v.z; As[c4 + 3][r] = v.w;
        }
        {
            int r = tx >> 4, c4 = (tx & 15) << 2;
            *reinterpret_cast<float4*>(&Bs[r][c4]) =
                *reinterpret_cast<const float4*>(tw1 + (size_t)(k0 + r) * H2 + col0 + c4);
        }
        __syncthreads();
#pragma unroll
        for (int k = 0; k < 16; k++) {
            float a[8], bb[4];
#pragma unroll
            for (int i = 0; i < 8; i++) a[i] = As[k][tr * 8 + i];
#pragma unroll
            for (int j = 0; j < 4; j++) bb[j] = Bs[k][tc * 4 + j];
#pragma unroll
            for (int i = 0; i < 8; i++)
#pragma unroll
                for (int j = 0; j < 4; j++) acc[i][j] += a[i] * bb[j];
        }
        __syncthreads();
    }
    float4 bv = *reinterpret_cast<const float4*>(b1 + col0 + tc * 4);
#pragma unroll
    for (int i = 0; i < 8; i++) {
        float4 o = make_float4(acc[i][0] + bv.x, acc[i][1] + bv.y,
                               acc[i][2] + bv.z, acc[i][3] + bv.w);
        *reinterpret_cast<float4*>(&g_pretau[(size_t)(row0 + tr * 8 + i) * H2 + col0 + tc * 4]) = o;
    }
}

// ---------------- conv pass: out = 0.99 * shortconv(x) -------------------
__global__ void conv_kernel(const float* __restrict__ X,
                            const float* __restrict__ cw,
                            float* __restrict__ out) {
    int idx = blockIdx.x * blockDim.x + threadIdx.x;
    if (idx >= Bb * Ss * (Hdim / 4)) return;
    int t = (idx >> 8) & (Ss - 1);
    int b = idx >> 19;
    int j = (idx & 255) << 2;
    float w[4][4];
#pragma unroll
    for (int r = 0; r < 4; r++) {
        float4 wr = *reinterpret_cast<const float4*>(cw + (j + r) * 4);
        w[r][0] = wr.x; w[r][1] = wr.y; w[r][2] = wr.z; w[r][3] = wr.w;
    }
    const float* xb = X + (size_t)b * Ss * Hdim;
    float4 acc = make_float4(0.f, 0.f, 0.f, 0.f);
#pragma unroll
    for (int k = 0; k < 4; k++) {
        int tt = t - 3 + k;
        if (tt >= 0) {
            float4 xv = *reinterpret_cast<const float4*>(xb + (size_t)tt * Hdim + j);
            acc.x += w[0][k] * xv.x; acc.y += w[1][k] * xv.y;
            acc.z += w[2][k] * xv.z; acc.w += w[3][k] * xv.w;
        }
    }
    acc.x *= (1.f - SCALEc); acc.y *= (1.f - SCALEc);
    acc.z *= (1.f - SCALEc); acc.w *= (1.f - SCALEc);
    *reinterpret_cast<float4*>(out + (size_t)idx * 4) = acc;
}

// ---------------- persistent liquid recurrence ---------------------------
// 96 co-resident blocks, ONE grid barrier per step. Every block keeps the
// full h in SMEM and applies the elementwise update redundantly; only the f
// vector (double-buffered) and 4 scalars per batch cross blocks.
__global__ void __launch_bounds__(NT, 1)
liquid_kernel(const float* __restrict__ X,
              const float* __restrict__ Wrec,
              const float* __restrict__ tw1,
              const float* __restrict__ tw2,
              const float* __restrict__ tb2p,
              const float* __restrict__ lngp,
              const float* __restrict__ lnbp,
              float* __restrict__ out) {
    extern __shared__ float sm[];
    float* w_s  = sm;                       // 16384
    float* h_s  = w_s + RPB * Hdim;         // 4096
    float* lng  = h_s + Bb * Hdim;          // 1024
    float* lnb  = lng + Hdim;               // 1024
    float* red  = lnb + Hdim;               // 128 (matvec partials / B-phase reduce)
    float* xpre = red + 128;                // 64
    float* w2s  = xpre + 64;                // 16
    float* shs  = w2s + 16;                 // 4
    float* shhs = shs + 4;                  // 4
    float* scal = shhs + 4;                 // 16 : a[4] oma[4] mu[4] rstd[4]

    const int tid  = threadIdx.x;
    const int warp = tid >> 5, lane = tid & 31;
    const int r0   = blockIdx.x * RPB;
    const bool isrec = (r0 < Hdim);
    const float tb2 = *tb2p;
    const unsigned NBu = gridDim.x;

    // ---- one-time: weights / ln params / zero h ----
    if (isrec) {
        for (int idx = tid; idx < RPB * (Hdim / 4); idx += NT) {
            int rl = idx >> 8; int i4 = (idx & 255) << 2;
            *reinterpret_cast<float4*>(&w_s[rl * Hdim + i4]) =
                *reinterpret_cast<const float4*>(Wrec + (size_t)(r0 + rl) * Hdim + i4);
        }
    } else {
        int m0 = r0 - Hdim;
        for (int idx = tid; idx < RPB * Hdim; idx += NT) {
            int rl = idx & (RPB - 1); int i = idx >> 4;   // transpose of tau_w1 bottom half
            w_s[rl * Hdim + i] = tw1[(size_t)(Hdim + i) * H2 + m0 + rl];
        }
        if (tid < RPB) w2s[tid] = tw2[r0 - Hdim + tid];
    }
    for (int i = tid; i < Hdim; i += NT) { lng[i] = lngp[i]; lnb[i] = lnbp[i]; }
    for (int i = tid; i < Bb * Hdim / 4; i += NT)
        *reinterpret_cast<float4*>(&h_s[i * 4]) = make_float4(0.f, 0.f, 0.f, 0.f);
    if (tid < 4) { shs[tid] = 0.f; shhs[tid] = 0.f; }
    __syncthreads();

    const int g  = warp >> 1;      // row group 0..3 (4 rows each)
    const int p  = warp & 1;       // column half
    const int rb = g * 4;

    for (int t = 0; t < Ss; t++) {
        const int par = t & 1;
        // ---- prefetch x_t / pretau for own rows (latency hidden by matvec) ----
        if (tid < 64) {
            int b = tid >> 4, rl = tid & 15;
            if (isrec) xpre[tid] = X[(size_t)(b * Ss + t) * Hdim + r0 + rl];
            else       xpre[tid] = g_pretau[(size_t)(b * Ss + t) * H2 + (r0 - Hdim) + rl];
        }

        // ---- Phase A: matvec. warp-pair = 4 rows x 4 batches, column-split ----
        float av[4][4];
#pragma unroll
        for (int r = 0; r < 4; r++)
#pragma unroll
            for (int b = 0; b < 4; b++) av[r][b] = 0.f;
#pragma unroll
        for (int c = 0; c < 4; c++) {
            int base = p * 512 + c * 128 + lane * 4;
            float4 w0 = *reinterpret_cast<const float4*>(&w_s[(rb + 0) * Hdim + base]);
            float4 w1 = *reinterpret_cast<const float4*>(&w_s[(rb + 1) * Hdim + base]);
            float4 w2 = *reinterpret_cast<const float4*>(&w_s[(rb + 2) * Hdim + base]);
            float4 w3 = *reinterpret_cast<const float4*>(&w_s[(rb + 3) * Hdim + base]);
#pragma unroll
            for (int b = 0; b < 4; b++) {
                float4 hv = *reinterpret_cast<const float4*>(&h_s[b * Hdim + base]);
                av[0][b] += w0.x * hv.x + w0.y * hv.y + w0.z * hv.z + w0.w * hv.w;
                av[1][b] += w1.x * hv.x + w1.y * hv.y + w1.z * hv.z + w1.w * hv.w;
                av[2][b] += w2.x * hv.x + w2.y * hv.y + w2.z * hv.z + w2.w * hv.w;
                av[3][b] += w3.x * hv.x + w3.y * hv.y + w3.z * hv.z + w3.w * hv.w;
            }
        }
#pragma unroll
        for (int r = 0; r < 4; r++)
#pragma unroll
            for (int b = 0; b < 4; b++) {
                float v = av[r][b];
#pragma unroll
                for (int off = 16; off > 0; off >>= 1) v += __shfl_down_sync(0xffffffffu, v, off);
                if (lane == 0) red[p * 64 + (rb + r) * 4 + b] = v;
            }
        __syncthreads();

        // ---- f/z + scalar partial atomics ----
        if (tid < 64) {
            int b = tid >> 4, rl = tid & 15;
            float d = red[rl * 4 + b] + red[64 + rl * 4 + b];
            float* accp = &g_acc[t * 32 + b * 8];
            if (isrec) {
                float f = tanhf(xpre[tid] + d);
                g_fz[par * (Bb * Hdim) + b * Hdim + r0 + rl] = f;
                float hv = h_s[b * Hdim + r0 + rl];
                float pf = f, pff = f * f, phf = hv * f;
#pragma unroll
                for (int off = 8; off > 0; off >>= 1) {
                    pf  += __shfl_down_sync(0xffffffffu, pf,  off, 16);
                    pff += __shfl_down_sync(0xffffffffu, pff, off, 16);
                    phf += __shfl_down_sync(0xffffffffu, phf, off, 16);
                }
                if (rl == 0) {
                    atomicAdd(accp + 1, pf);
                    atomicAdd(accp + 2, pff);
                    atomicAdd(accp + 3, phf);
                }
            } else {
                float z = tanhf(xpre[tid] + d);
                float pz = z * w2s[rl];
#pragma unroll
                for (int off = 8; off > 0; off >>= 1)
                    pz += __shfl_down_sync(0xffffffffu, pz, off, 16);
                if (rl == 0) atomicAdd(accp + 0, pz);
            }
        }
        __threadfence();
        __syncthreads();

        // ---- single grid barrier ----
        if (tid == 0) {
            atomicAdd(&g_bar, 1u);
            unsigned target = (unsigned)(t + 1) * NBu, v;
            do { asm volatile("ld.acquire.gpu.u32 %0, [%1];" : "=r"(v) : "l"(&g_bar) : "memory"); }
            while (v < target);
        }
        __syncthreads();

        // ---- Phase B: tau + analytic LN coefficients (all blocks, redundant) ----
        if (tid < 4) {
            const float* accp = &g_acc[t * 32 + tid * 8];
            float Zt  = __ldcg(accp + 0);
            float Sf  = __ldcg(accp + 1);
            float Sff = __ldcg(accp + 2);
            float Shf = __ldcg(accp + 3);
            float sig = 1.f / (1.f + expf(-(Zt + tb2)));
            float tau = 1.f + 4.f * sig;
            float a = DTc / tau, oma = 1.f - a;
            float mu  = (oma * shs[tid] + a * Sf) * (1.f / (float)Hdim);
            float sy2 = oma * oma * shhs[tid] + 2.f * a * oma * Shf + a * a * Sff;
            float var = sy2 * (1.f / (float)Hdim) - mu * mu;
            scal[tid] = a; scal[4 + tid] = oma; scal[8 + tid] = mu;
            scal[12 + tid] = rsqrtf(var + 1e-5f);
        }
        __syncthreads();

        // ---- full local h update + next-step Sh/Shh reduction ----
        {
            const int j4 = tid * 4;
            float4 g4 = *reinterpret_cast<const float4*>(&lng[j4]);
            float4 b4 = *reinterpret_cast<const float4*>(&lnb[j4]);
            float psh[4], pshh[4];
#pragma unroll
            for (int b = 0; b < 4; b++) {
                float a = scal[b], oma = scal[4 + b], mu = scal[8 + b], rs = scal[12 + b];
                float4 f4 = __ldcg(reinterpret_cast<const float4*>(
                                &g_fz[par * (Bb * Hdim) + b * Hdim + j4]));
                float4 h4 = *reinterpret_cast<const float4*>(&h_s[b * Hdim + j4]);
                float4 hn;
                hn.x = (oma * h4.x + a * f4.x - mu) * rs * g4.x + b4.x;
                hn.y = (oma * h4.y + a * f4.y - mu) * rs * g4.y + b4.y;
                hn.z = (oma * h4.z + a * f4.z - mu) * rs * g4.z + b4.z;
                hn.w = (oma * h4.w + a * f4.w - mu) * rs * g4.w + b4.w;
                *reinterpret_cast<float4*>(&h_s[b * Hdim + j4]) = hn;
                psh[b]  = hn.x + hn.y + hn.z + hn.w;
                pshh[b] = hn.x * hn.x + hn.y * hn.y + hn.z * hn.z + hn.w * hn.w;
            }
#pragma unroll
            for (int b = 0; b < 4; b++) {
                float v1 = psh[b], v2 = pshh[b];
#pragma unroll
                for (int off = 16; off > 0; off >>= 1) {
                    v1 += __shfl_down_sync(0xffffffffu, v1, off);
                    v2 += __shfl_down_sync(0xffffffffu, v2, off);
                }
                if (lane == 0) { red[warp * 8 + b] = v1; red[warp * 8 + 4 + b] = v2; }
            }
        }
        __syncthreads();
        if (tid < 8) {
            float s = 0.f;
#pragma unroll
            for (int w = 0; w < 8; w++) s += red[w * 8 + tid];
            if (tid < 4) shs[tid] = s; else shhs[tid - 4] = s;
        }
        // ---- own-row output write (rec blocks only) ----
        if (isrec && tid < 64) {
            int b = tid >> 4, rl = tid & 15;
            float hn = h_s[b * Hdim + r0 + rl];
            size_t o = (size_t)(b * Ss + t) * Hdim + r0 + rl;
            out[o] = out[o] + SCALEc * hn;        // out pre-filled with 0.99*sc
        }
        __syncthreads();
    }
}

// ---------------- launch --------------------------------------------------
extern "C" void kernel_launch(void* const* d_in, const int* in_sizes, int n_in,
                              void* d_out, int out_size) {
    const float* X   = (const float*)d_in[0];
    const float* cw  = (const float*)d_in[1];
    const float* Wr  = (const float*)d_in[2];
    const float* tw1 = (const float*)d_in[3];
    const float* tb1 = (const float*)d_in[4];
    const float* tw2 = (const float*)d_in[5];
    const float* tb2 = (const float*)d_in[6];
    const float* lg  = (const float*)d_in[7];
    const float* lb  = (const float*)d_in[8];
    float* out = (float*)d_out;

    const int smem_bytes = (RPB * Hdim + Bb * Hdim + Hdim + Hdim + 128 + 64 + 16 + 4 + 4 + 16) * 4;
    cudaFuncSetAttribute(liquid_kernel, cudaFuncAttributeMaxDynamicSharedMemorySize, smem_bytes);

    reset_kernel<<<256, 256>>>();

    dim3 ggrid(H2 / 64, (Bb * Ss) / 128);
    pretau_gemm<<<ggrid, 256>>>(X, tw1, tb1);

    conv_kernel<<<(Bb * Ss * (Hdim / 4)) / 256, 256>>>(X, cw, out);

    liquid_kernel<<<NBLK, NT, smem_bytes>>>(X, Wr, tw1, tw2, tb2, lg, lb, out);
}

// round 7
// speedup vs baseline: 1.3159x; 1.0126x over previous
#include <cuda_runtime.h>

#define Hdim 1024
#define H2   512
#define Bb   4
#define Ss   2048
#define NBLK 96
#define RPB  16      // weight rows per block (96*16 = 1536 = 1024 rec + 512 tau)
#define NT   256     // 8 warps
#define DTc  0.1f
#define SCALEc 0.01f

// ---------------- device scratch (static, no allocation) ----------------
__device__ float    g_fz[2 * Bb * Hdim];       // double-buffered f vector (rec rows)
__device__ float    g_part[2][16 * NBLK];      // double-buffered per-block scalar partials
__device__ float    g_pretau[(size_t)Bb * Ss * H2]; // x-part of tau MLP (16MB)
__device__ unsigned g_bar;                     // monotonic grid barrier

// ---------------- reset (runs every launch; graph-replay safe) ----------
__global__ void reset_kernel() {
    if (threadIdx.x == 0) g_bar = 0u;
}

// ---------------- pre-tau GEMM: C[p][m] = b1[m] + sum_i X[p][i]*tw1[i][m] ---
__global__ void pretau_gemm(const float* __restrict__ X,
                            const float* __restrict__ tw1,
                            const float* __restrict__ b1) {
    __shared__ float As[16][128];
    __shared__ float Bs[16][64];
    const int tx = threadIdx.x;                  // 256 threads
    const int row0 = blockIdx.y * 128;
    const int col0 = blockIdx.x * 64;
    const int tr = tx >> 4, tc = tx & 15;        // 16x16 thread grid, 8x4 micro-tile
    float acc[8][4];
#pragma unroll
    for (int i = 0; i < 8; i++)
#pragma unroll
        for (int j = 0; j < 4; j++) acc[i][j] = 0.f;

    for (int k0 = 0; k0 < Hdim; k0 += 16) {
#pragma unroll
        for (int l = 0; l < 2; l++) {
            int f = tx + l * 256;
            int r = f >> 2, c4 = (f & 3) << 2;
            float4 v = *reinterpret_cast<const float4*>(X + (size_t)(row0 + r) * Hdim + k0 + c4);
            As[c4 + 0][r] = v.x; As[c4 + 1][r] = v.y; As[c4 + 2][r] = v.z; As[c4 + 3][r] = v.w;
        }
        {
            int r = tx >> 4, c4 = (tx & 15) << 2;
            *reinterpret_cast<float4*>(&Bs[r][c4]) =
                *reinterpret_cast<const float4*>(tw1 + (size_t)(k0 + r) * H2 + col0 + c4);
        }
        __syncthreads();
#pragma unroll
        for (int k = 0; k < 16; k++) {
            float a[8], bb[4];
#pragma unroll
            for (int i = 0; i < 8; i++) a[i] = As[k][tr * 8 + i];
#pragma unroll
            for (int j = 0; j < 4; j++) bb[j] = Bs[k][tc * 4 + j];
#pragma unroll
            for (int i = 0; i < 8; i++)
#pragma unroll
                for (int j = 0; j < 4; j++) acc[i][j] += a[i] * bb[j];
        }
        __syncthreads();
    }
    float4 bv = *reinterpret_cast<const float4*>(b1 + col0 + tc * 4);
#pragma unroll
    for (int i = 0; i < 8; i++) {
        float4 o = make_float4(acc[i][0] + bv.x, acc[i][1] + bv.y,
                               acc[i][2] + bv.z, acc[i][3] + bv.w);
        *reinterpret_cast<float4*>(&g_pretau[(size_t)(row0 + tr * 8 + i) * H2 + col0 + tc * 4]) = o;
    }
}

// ---------------- conv pass: out = 0.99 * shortconv(x) -------------------
__global__ void conv_kernel(const float* __restrict__ X,
                            const float* __restrict__ cw,
                            float* __restrict__ out) {
    int idx = blockIdx.x * blockDim.x + threadIdx.x;
    if (idx >= Bb * Ss * (Hdim / 4)) return;
    int t = (idx >> 8) & (Ss - 1);
    int b = idx >> 19;
    int j = (idx & 255) << 2;
    float w[4][4];
#pragma unroll
    for (int r = 0; r < 4; r++) {
        float4 wr = *reinterpret_cast<const float4*>(cw + (j + r) * 4);
        w[r][0] = wr.x; w[r][1] = wr.y; w[r][2] = wr.z; w[r][3] = wr.w;
    }
    const float* xb = X + (size_t)b * Ss * Hdim;
    float4 acc = make_float4(0.f, 0.f, 0.f, 0.f);
#pragma unroll
    for (int k = 0; k < 4; k++) {
        int tt = t - 3 + k;
        if (tt >= 0) {
            float4 xv = *reinterpret_cast<const float4*>(xb + (size_t)tt * Hdim + j);
            acc.x += w[0][k] * xv.x; acc.y += w[1][k] * xv.y;
            acc.z += w[2][k] * xv.z; acc.w += w[3][k] * xv.w;
        }
    }
    acc.x *= (1.f - SCALEc); acc.y *= (1.f - SCALEc);
    acc.z *= (1.f - SCALEc); acc.w *= (1.f - SCALEc);
    *reinterpret_cast<float4*>(out + (size_t)idx * 4) = acc;
}

// ---------------- persistent liquid recurrence ---------------------------
// 96 co-resident blocks, ONE grid barrier per step. Every block keeps the
// full h in SMEM; only f (double-buffered) and per-block scalar partials
// (double-buffered, NO atomics) cross blocks.
__global__ void __launch_bounds__(NT, 1)
liquid_kernel(const float* __restrict__ X,
              const float* __restrict__ Wrec,
              const float* __restrict__ tw1,
              const float* __restrict__ tw2,
              const float* __restrict__ tb2p,
              const float* __restrict__ lngp,
              const float* __restrict__ lnbp,
              float* __restrict__ out) {
    extern __shared__ float sm[];
    float* w_s  = sm;                       // 16384
    float* h_s  = w_s + RPB * Hdim;         // 4096
    float* lng  = h_s + Bb * Hdim;          // 1024
    float* lnb  = lng + Hdim;               // 1024
    float* red  = lnb + Hdim;               // 128 (matvec partials / B-phase reduce)
    float* xpre = red + 128;                // 64
    float* w2s  = xpre + 64;                // 16
    float* shs  = w2s + 16;                 // 4
    float* shhs = shs + 4;                  // 4
    float* scal = shhs + 4;                 // 16 : a[4] oma[4] mu[4] rstd[4]

    const int tid  = threadIdx.x;
    const int warp = tid >> 5, lane = tid & 31;
    const int r0   = blockIdx.x * RPB;
    const bool isrec = (r0 < Hdim);
    const float tb2 = *tb2p;
    const unsigned NBu = gridDim.x;

    // ---- one-time: weights / ln params / zero h ----
    if (isrec) {
        for (int idx = tid; idx < RPB * (Hdim / 4); idx += NT) {
            int rl = idx >> 8; int i4 = (idx & 255) << 2;
            *reinterpret_cast<float4*>(&w_s[rl * Hdim + i4]) =
                *reinterpret_cast<const float4*>(Wrec + (size_t)(r0 + rl) * Hdim + i4);
        }
    } else {
        int m0 = r0 - Hdim;
        for (int idx = tid; idx < RPB * Hdim; idx += NT) {
            int rl = idx & (RPB - 1); int i = idx >> 4;   // transpose of tau_w1 bottom half
            w_s[rl * Hdim + i] = tw1[(size_t)(Hdim + i) * H2 + m0 + rl];
        }
        if (tid < RPB) w2s[tid] = tw2[r0 - Hdim + tid];
    }
    for (int i = tid; i < Hdim; i += NT) { lng[i] = lngp[i]; lnb[i] = lnbp[i]; }
    for (int i = tid; i < Bb * Hdim / 4; i += NT)
        *reinterpret_cast<float4*>(&h_s[i * 4]) = make_float4(0.f, 0.f, 0.f, 0.f);
    if (tid < 4) { shs[tid] = 0.f; shhs[tid] = 0.f; }
    __syncthreads();

    const int g  = warp >> 1;      // row group 0..3 (4 rows each)
    const int p  = warp & 1;       // column half
    const int rb = g * 4;

    for (int t = 0; t < Ss; t++) {
        const int par = t & 1;
        // ---- prefetch x_t / pretau for own rows (latency hidden by matvec) ----
        if (tid < 64) {
            int b = tid >> 4, rl = tid & 15;
            if (isrec) xpre[tid] = X[(size_t)(b * Ss + t) * Hdim + r0 + rl];
            else       xpre[tid] = g_pretau[(size_t)(b * Ss + t) * H2 + (r0 - Hdim) + rl];
        }

        // ---- Phase A: matvec. warp-pair = 4 rows x 4 batches, column-split ----
        float av[4][4];
#pragma unroll
        for (int r = 0; r < 4; r++)
#pragma unroll
            for (int b = 0; b < 4; b++) av[r][b] = 0.f;
#pragma unroll
        for (int c = 0; c < 4; c++) {
            int base = p * 512 + c * 128 + lane * 4;
            float4 w0 = *reinterpret_cast<const float4*>(&w_s[(rb + 0) * Hdim + base]);
            float4 w1 = *reinterpret_cast<const float4*>(&w_s[(rb + 1) * Hdim + base]);
            float4 w2 = *reinterpret_cast<const float4*>(&w_s[(rb + 2) * Hdim + base]);
            float4 w3 = *reinterpret_cast<const float4*>(&w_s[(rb + 3) * Hdim + base]);
#pragma unroll
            for (int b = 0; b < 4; b++) {
                float4 hv = *reinterpret_cast<const float4*>(&h_s[b * Hdim + base]);
                av[0][b] += w0.x * hv.x + w0.y * hv.y + w0.z * hv.z + w0.w * hv.w;
                av[1][b] += w1.x * hv.x + w1.y * hv.y + w1.z * hv.z + w1.w * hv.w;
                av[2][b] += w2.x * hv.x + w2.y * hv.y + w2.z * hv.z + w2.w * hv.w;
                av[3][b] += w3.x * hv.x + w3.y * hv.y + w3.z * hv.z + w3.w * hv.w;
            }
        }
#pragma unroll
        for (int r = 0; r < 4; r++)
#pragma unroll
            for (int b = 0; b < 4; b++) {
                float v = av[r][b];
#pragma unroll
                for (int off = 16; off > 0; off >>= 1) v += __shfl_down_sync(0xffffffffu, v, off);
                if (lane == 0) red[p * 64 + (rb + r) * 4 + b] = v;
            }
        __syncthreads();

        // ---- f/z + per-block scalar partial stores (NO atomics) ----
        if (tid < 64) {
            int b = tid >> 4, rl = tid & 15;
            float d = red[rl * 4 + b] + red[64 + rl * 4 + b];
            float* P = &g_part[par][0];
            if (isrec) {
                float f = tanhf(xpre[tid] + d);
                g_fz[par * (Bb * Hdim) + b * Hdim + r0 + rl] = f;
                float hv = h_s[b * Hdim + r0 + rl];
                float pf = f, pff = f * f, phf = hv * f;
#pragma unroll
                for (int off = 8; off > 0; off >>= 1) {
                    pf  += __shfl_down_sync(0xffffffffu, pf,  off, 16);
                    pff += __shfl_down_sync(0xffffffffu, pff, off, 16);
                    phf += __shfl_down_sync(0xffffffffu, phf, off, 16);
                }
                if (rl == 0) {
                    P[(b * 4 + 1) * NBLK + blockIdx.x] = pf;
                    P[(b * 4 + 2) * NBLK + blockIdx.x] = pff;
                    P[(b * 4 + 3) * NBLK + blockIdx.x] = phf;
                }
            } else {
                float z = tanhf(xpre[tid] + d);
                float pz = z * w2s[rl];
#pragma unroll
                for (int off = 8; off > 0; off >>= 1)
                    pz += __shfl_down_sync(0xffffffffu, pz, off, 16);
                if (rl == 0) P[(b * 4 + 0) * NBLK + blockIdx.x] = pz;
            }
        }
        __threadfence();
        __syncthreads();

        // ---- single grid barrier ----
        if (tid == 0) {
            atomicAdd(&g_bar, 1u);
            unsigned target = (unsigned)(t + 1) * NBu, v;
            do { asm volatile("ld.acquire.gpu.u32 %0, [%1];" : "=r"(v) : "l"(&g_bar) : "memory"); }
            while (v < target);
        }
        __syncthreads();

        // ---- Phase B: prefetch f into registers FIRST (overlaps scalar work) ----
        float4 f4r[4];
#pragma unroll
        for (int b = 0; b < 4; b++)
            f4r[b] = __ldcg(reinterpret_cast<const float4*>(
                         &g_fz[par * (Bb * Hdim) + b * Hdim + tid * 4]));

        // ---- cross-block scalar reduction: warp b handles batch b ----
        if (warp < 4) {
            const int b = warp;
            const float* P = &g_part[par][0];
            float z   = __ldcg(&P[(b * 4 + 0) * NBLK + 64 + lane]);              // 32 tau blocks
            float sf  = __ldcg(&P[(b * 4 + 1) * NBLK + lane])
                      + __ldcg(&P[(b * 4 + 1) * NBLK + 32 + lane]);              // 64 rec blocks
            float sff = __ldcg(&P[(b * 4 + 2) * NBLK + lane])
                      + __ldcg(&P[(b * 4 + 2) * NBLK + 32 + lane]);
            float shf = __ldcg(&P[(b * 4 + 3) * NBLK + lane])
                      + __ldcg(&P[(b * 4 + 3) * NBLK + 32 + lane]);
#pragma unroll
            for (int off = 16; off > 0; off >>= 1) {
                z   += __shfl_down_sync(0xffffffffu, z,   off);
                sf  += __shfl_down_sync(0xffffffffu, sf,  off);
                sff += __shfl_down_sync(0xffffffffu, sff, off);
                shf += __shfl_down_sync(0xffffffffu, shf, off);
            }
            if (lane == 0) {
                float sig = 1.f / (1.f + expf(-(z + tb2)));
                float tau = 1.f + 4.f * sig;
                float a = DTc / tau, oma = 1.f - a;
                float mu  = (oma * shs[b] + a * sf) * (1.f / (float)Hdim);
                float sy2 = oma * oma * shhs[b] + 2.f * a * oma * shf + a * a * sff;
                float var = sy2 * (1.f / (float)Hdim) - mu * mu;
                scal[b] = a; scal[4 + b] = oma; scal[8 + b] = mu;
                scal[12 + b] = rsqrtf(var + 1e-5f);
            }
        }
        __syncthreads();

        // ---- full local h update + next-step Sh/Shh reduction ----
        {
            const int j4 = tid * 4;
            float4 g4 = *reinterpret_cast<const float4*>(&lng[j4]);
            float4 b4 = *reinterpret_cast<const float4*>(&lnb[j4]);
            float psh[4], pshh[4];
#pragma unroll
            for (int b = 0; b < 4; b++) {
                float a = scal[b], oma = scal[4 + b], mu = scal[8 + b], rs = scal[12 + b];
                float4 f4 = f4r[b];
                float4 h4 = *reinterpret_cast<const float4*>(&h_s[b * Hdim + j4]);
                float4 hn;
                hn.x = (oma * h4.x + a * f4.x - mu) * rs * g4.x + b4.x;
                hn.y = (oma * h4.y + a * f4.y - mu) * rs * g4.y + b4.y;
                hn.z = (oma * h4.z + a * f4.z - mu) * rs * g4.z + b4.z;
                hn.w = (oma * h4.w + a * f4.w - mu) * rs * g4.w + b4.w;
                *reinterpret_cast<float4*>(&h_s[b * Hdim + j4]) = hn;
                psh[b]  = hn.x + hn.y + hn.z + hn.w;
                pshh[b] = hn.x * hn.x + hn.y * hn.y + hn.z * hn.z + hn.w * hn.w;
            }
#pragma unroll
            for (int b = 0; b < 4; b++) {
                float v1 = psh[b], v2 = pshh[b];
#pragma unroll
                for (int off = 16; off > 0; off >>= 1) {
                    v1 += __shfl_down_sync(0xffffffffu, v1, off);
                    v2 += __shfl_down_sync(0xffffffffu, v2, off);
                }
                if (lane == 0) { red[warp * 8 + b] = v1; red[warp * 8 + 4 + b] = v2; }
            }
        }
        __syncthreads();
        if (tid < 8) {
            float s = 0.f;
#pragma unroll
            for (int w = 0; w < 8; w++) s += red[w * 8 + tid];
            if (tid < 4) shs[tid] = s; else shhs[tid - 4] = s;
        }
        // ---- own-row output write (rec blocks only) ----
        if (isrec && tid < 64) {
            int b = tid >> 4, rl = tid & 15;
            float hn = h_s[b * Hdim + r0 + rl];
            size_t o = (size_t)(b * Ss + t) * Hdim + r0 + rl;
            out[o] = out[o] + SCALEc * hn;        // out pre-filled with 0.99*sc
        }
        __syncthreads();
    }
}

// ---------------- launch --------------------------------------------------
extern "C" void kernel_launch(void* const* d_in, const int* in_sizes, int n_in,
                              void* d_out, int out_size) {
    const float* X   = (const float*)d_in[0];
    const float* cw  = (const float*)d_in[1];
    const float* Wr  = (const float*)d_in[2];
    const float* tw1 = (const float*)d_in[3];
    const float* tb1 = (const float*)d_in[4];
    const float* tw2 = (const float*)d_in[5];
    const float* tb2 = (const float*)d_in[6];
    const float* lg  = (const float*)d_in[7];
    const float* lb  = (const float*)d_in[8];
    float* out = (float*)d_out;

    const int smem_bytes = (RPB * Hdim + Bb * Hdim + Hdim + Hdim + 128 + 64 + 16 + 4 + 4 + 16) * 4;
    cudaFuncSetAttribute(liquid_kernel, cudaFuncAttributeMaxDynamicSharedMemorySize, smem_bytes);

    reset_kernel<<<1, 32>>>();

    dim3 ggrid(H2 / 64, (Bb * Ss) / 128);
    pretau_gemm<<<ggrid, 256>>>(X, tw1, tb1);

    conv_kernel<<<(Bb * Ss * (Hdim / 4)) / 256, 256>>>(X, cw, out);

    liquid_kernel<<<NBLK, NT, smem_bytes>>>(X, Wr, tw1, tw2, tb2, lg, lb, out);
}